// round 4
// baseline (speedup 1.0000x reference)
#include <cuda_runtime.h>

// ---------------------------------------------------------------------------
// MIND loss, fully fused. R4: register-cached unshifted taps + exact retile.
//  - pred/gt packed into f32x2 (FFMA2): one packed op handles both images
//  - pa[14] (unshifted conv taps) cached in registers across all 198 iters
//  - TILE 26x64 -> 32 conv rows x 8 octets = exactly 256 row-stage units
//  - 64-bit smem accesses conflict-free per 16-lane phase (odd pitches 81/67)
//  - M/max(M) == exp((Dmin - D)/V)  -> two passes over the 99 shifts
// ---------------------------------------------------------------------------

typedef unsigned long long u64;

namespace {
constexpr int HIMG = 384;
constexpr int WIMG = 384;
constexpr int BATCH = 4;
constexpr int INNER = 370;          // 384 - 2*7
constexpr int TILE_H = 26;
constexpr int TILE_W = 64;
constexpr int CH = 32;              // conv-support rows = TILE_H + 6
constexpr int RH = 41;              // img tile rows (max access r+4+5 = 40)
constexpr int RW = 79;              // img tile cols
constexpr int IP2 = 81;             // img pitch (float2 units, odd)
constexpr int RP2 = 67;             // row-buf pitch (float2 units, odd)
constexpr int NTHREADS = 256;
constexpr int TILES_X = 6;          // 6*64  = 384 >= 370
constexpr int TILES_Y = 15;         // 15*26 = 390 >= 370
constexpr int NCTAS = BATCH * TILES_X * TILES_Y;   // 360
constexpr int SMEM_U64 = RH * IP2 + 2 * CH * RP2;  // img + 2 row bufs
constexpr int SMEM_BYTES = SMEM_U64 * 8;           // 60872 B

constexpr double E98 = 0.32465246735834974;   // exp(-9/8)
constexpr double E48 = 0.60653065971263342;   // exp(-4/8)
constexpr double E18 = 0.88249690258459546;   // exp(-1/8)
constexpr double TPS = 25.132741228718345;    // 8*pi
constexpr float GX0 = (float)E98;
constexpr float GX1 = (float)E48;
constexpr float GX2 = (float)E18;             // center tap == 1
constexpr float GY0 = (float)(E98 / TPS);
constexpr float GY1 = (float)(E48 / TPS);
constexpr float GY2 = (float)(E18 / TPS);
constexpr float GY3 = (float)(1.0 / TPS);
}  // namespace

__device__ float g_partials[NCTAS];

// ---- packed f32x2 helpers (sm_100+) ----
__device__ __forceinline__ u64 bc2(float x) {
  u64 r; asm("mov.b64 %0,{%1,%1};" : "=l"(r) : "f"(x)); return r;
}
__device__ __forceinline__ u64 pk2(float a, float b) {
  u64 r; asm("mov.b64 %0,{%1,%2};" : "=l"(r) : "f"(a), "f"(b)); return r;
}
__device__ __forceinline__ void up2(u64 v, float& a, float& b) {
  asm("mov.b64 {%0,%1},%2;" : "=f"(a), "=f"(b) : "l"(v));
}
__device__ __forceinline__ u64 f2sub(u64 a, u64 b) {
  u64 r; asm("sub.rn.f32x2 %0,%1,%2;" : "=l"(r) : "l"(a), "l"(b)); return r;
}
__device__ __forceinline__ u64 f2mul(u64 a, u64 b) {
  u64 r; asm("mul.rn.f32x2 %0,%1,%2;" : "=l"(r) : "l"(a), "l"(b)); return r;
}
__device__ __forceinline__ u64 f2add(u64 a, u64 b) {
  u64 r; asm("add.rn.f32x2 %0,%1,%2;" : "=l"(r) : "l"(a), "l"(b)); return r;
}
__device__ __forceinline__ u64 f2fma(u64 a, u64 b, u64 c) {
  u64 r; asm("fma.rn.f32x2 %0,%1,%2,%3;" : "=l"(r) : "l"(a), "l"(b), "l"(c));
  return r;
}

// Fused diffsq + horizontal 7-tap conv; pa taps come from registers.
__device__ __forceinline__ void row_stage(const u64 pa[14],
                                          const u64* __restrict__ pb,
                                          u64* __restrict__ pr,
                                          u64 gx0, u64 gx1, u64 gx2) {
  u64 dsq[14];
#pragma unroll
  for (int k = 0; k < 14; k++) {
    u64 d = f2sub(pa[k], pb[k]);
    dsq[k] = f2mul(d, d);
  }
#pragma unroll
  for (int c = 0; c < 8; c++) {
    u64 v = f2mul(gx0, dsq[c]);
    v = f2fma(gx1, dsq[c + 1], v);
    v = f2fma(gx2, dsq[c + 2], v);
    v = f2add(v, dsq[c + 3]);  // center tap weight == 1
    v = f2fma(gx2, dsq[c + 4], v);
    v = f2fma(gx1, dsq[c + 5], v);
    v = f2fma(gx0, dsq[c + 6], v);
    pr[c] = v;
  }
}

__device__ __forceinline__ u64 col7(const u64* rv, int i,
                                    u64 gy0, u64 gy1, u64 gy2, u64 gy3) {
  u64 v = f2mul(gy0, rv[i]);
  v = f2fma(gy1, rv[i + 1], v);
  v = f2fma(gy2, rv[i + 2], v);
  v = f2fma(gy3, rv[i + 3], v);
  v = f2fma(gy2, rv[i + 4], v);
  v = f2fma(gy1, rv[i + 5], v);
  v = f2fma(gy0, rv[i + 6], v);
  return v;
}

template <int N>
__device__ __forceinline__ void colA(const u64* __restrict__ bufc, int off,
                                     bool card, float* DmP, float* DmG,
                                     float* Vp, float* Vg,
                                     u64 gy0, u64 gy1, u64 gy2, u64 gy3) {
  u64 rv[N + 6];
#pragma unroll
  for (int i = 0; i < N + 6; i++) rv[i] = bufc[off + i * RP2];
#pragma unroll
  for (int i = 0; i < N; i++) {
    u64 D2 = col7(rv, i, gy0, gy1, gy2, gy3);
    float dp, dg; up2(D2, dp, dg);
    DmP[i] = fminf(DmP[i], dp);
    DmG[i] = fminf(DmG[i], dg);
    if (card) { Vp[i] += dp; Vg[i] += dg; }
  }
}

template <int N>
__device__ __forceinline__ float colB(const u64* __restrict__ bufc, int off,
                                      const u64* Dmin2, const u64* invV2,
                                      int py0, bool cOK,
                                      u64 gy0, u64 gy1, u64 gy2, u64 gy3) {
  u64 rv[N + 6];
#pragma unroll
  for (int i = 0; i < N + 6; i++) rv[i] = bufc[off + i * RP2];
  float acc = 0.f;
#pragma unroll
  for (int i = 0; i < N; i++) {
    u64 D2 = col7(rv, i, gy0, gy1, gy2, gy3);
    u64 e2 = f2mul(f2sub(Dmin2[i], D2), invV2[i]);
    float ep, eg; up2(e2, ep, eg);
    float mp = __expf(ep);
    float mg = __expf(eg);
    if (cOK && (py0 + i) < INNER) acc += fabsf(mp - mg);
  }
  return acc;
}

__device__ __forceinline__ void decode_shift(int si, int& sx, int& sy) {
  int t = si < 55 ? si : si + 1;   // skip (0,0) at index 55
  int q = t / 10;                  // x outer, y inner (matches reference)
  sx = q - 5;
  sy = t - q * 10 - 5;
}

extern "C" __global__ void __launch_bounds__(NTHREADS, 2)
mind_main(const float* __restrict__ pred, const float* __restrict__ gt) {
  extern __shared__ u64 smem[];
  u64* sImg = smem;
  u64* buf[2] = {smem + RH * IP2, smem + RH * IP2 + CH * RP2};

  const int tX = blockIdx.x, tY = blockIdx.y, b = blockIdx.z;
  const int tid = threadIdx.x;
  const float* imgP = pred + b * HIMG * WIMG;
  const float* imgG = gt + b * HIMG * WIMG;

  // Load tile + halo (circular wrap), interleaving P/G into float2.
  float2* sImgF = (float2*)sImg;
  for (int i = tid; i < RH * RW; i += NTHREADS) {
    int rr = i / RW, c2 = i - rr * RW;
    int gr = tY * TILE_H + rr; if (gr >= HIMG) gr -= HIMG;
    int gc = tX * TILE_W + c2; if (gc >= WIMG) gc -= WIMG;
    sImgF[rr * IP2 + c2] = make_float2(imgP[gr * WIMG + gc],
                                       imgG[gr * WIMG + gc]);
  }
  __syncthreads();

  // Row-stage unit: conflict-free per 16-lane phase.
  const int w = tid >> 5, l = tid & 31;
  const int j = ((l >> 3) & 3) | ((w & 1) << 2);
  const int r = (l & 7) | ((w >> 1) << 3);
  const u64* paPtr = sImg + (r + 4) * IP2 + (j * 8 + 4);
  u64* prB[2] = {buf[0] + r * RP2 + j * 8, buf[1] + r * RP2 + j * 8};

  // Cache the shift-invariant taps in registers (reused 198 times).
  u64 pa[14];
#pragma unroll
  for (int k = 0; k < 14; k++) pa[k] = paPtr[k];

  // Col-stage ownership: 64 cols x 4 uneven row groups (7,7,6,6).
  const int cc = tid & 63;
  const int gg = tid >> 6;
  const int rbase = (gg < 2) ? 7 * gg : 14 + 6 * (gg - 2);
  const int coff = rbase * RP2 + cc;
  const bool cOK = (tX * TILE_W + cc) < INNER;
  const int py0 = tY * TILE_H + rbase;

  const u64 gx0 = bc2(GX0), gx1 = bc2(GX1), gx2 = bc2(GX2);
  const u64 gy0 = bc2(GY0), gy1 = bc2(GY1), gy2 = bc2(GY2), gy3 = bc2(GY3);

  float DmP[7], DmG[7], Vp[7], Vg[7];
#pragma unroll
  for (int i = 0; i < 7; i++) {
    DmP[i] = 3e38f; DmG[i] = 3e38f; Vp[i] = 0.f; Vg[i] = 0.f;
  }

  int sx, sy;

  // ---------------- Pass A: Dmin and cardinal sum -> invV ----------------
  decode_shift(0, sx, sy);
  row_stage(pa, paPtr - sy * IP2 - sx, prB[0], gx0, gx1, gx2);
  __syncthreads();
  for (int si = 0; si < 99; si++) {
    int cur = si & 1;
    decode_shift(si, sx, sy);
    bool card = ((sx == 0) & ((sy == 1) | (sy == -1))) |
                ((sy == 0) & ((sx == 1) | (sx == -1)));
    if (gg < 2) colA<7>(buf[cur], coff, card, DmP, DmG, Vp, Vg, gy0, gy1, gy2, gy3);
    else        colA<6>(buf[cur], coff, card, DmP, DmG, Vp, Vg, gy0, gy1, gy2, gy3);
    if (si + 1 < 99) {
      int nsx, nsy;
      decode_shift(si + 1, nsx, nsy);
      row_stage(pa, paPtr - nsy * IP2 - nsx, prB[cur ^ 1], gx0, gx1, gx2);
    }
    __syncthreads();
  }
  u64 Dmin2[7], invV2[7];
#pragma unroll
  for (int i = 0; i < 7; i++) {
    Dmin2[i] = pk2(DmP[i], DmG[i]);
    invV2[i] = pk2(1.0f / (Vp[i] * 0.25f + 1e-5f),
                   1.0f / (Vg[i] * 0.25f + 1e-5f));
  }

  // ---------------- Pass B: accumulate |Mp - Mg| ----------------
  float acc = 0.f;
  decode_shift(0, sx, sy);
  row_stage(pa, paPtr - sy * IP2 - sx, prB[0], gx0, gx1, gx2);
  __syncthreads();
  for (int si = 0; si < 99; si++) {
    int cur = si & 1;
    if (gg < 2) acc += colB<7>(buf[cur], coff, Dmin2, invV2, py0, cOK, gy0, gy1, gy2, gy3);
    else        acc += colB<6>(buf[cur], coff, Dmin2, invV2, py0, cOK, gy0, gy1, gy2, gy3);
    if (si + 1 < 99) {
      int nsx, nsy;
      decode_shift(si + 1, nsx, nsy);
      row_stage(pa, paPtr - nsy * IP2 - nsx, prB[cur ^ 1], gx0, gx1, gx2);
    }
    __syncthreads();
  }

  // Deterministic per-CTA reduction.
#pragma unroll
  for (int o = 16; o > 0; o >>= 1) acc += __shfl_down_sync(0xffffffffu, acc, o);
  float* red = (float*)smem;   // passes done; safe reuse
  if ((tid & 31) == 0) red[tid >> 5] = acc;
  __syncthreads();
  if (tid == 0) {
    float s = 0.f;
#pragma unroll
    for (int ww = 0; ww < NTHREADS / 32; ww++) s += red[ww];
    g_partials[(b * TILES_Y + tY) * TILES_X + tX] = s;
  }
}

extern "C" __global__ void mind_reduce(float* __restrict__ out) {
  int tid = threadIdx.x;
  float s = 0.f;
  for (int i = tid; i < NCTAS; i += 256) s += g_partials[i];
#pragma unroll
  for (int o = 16; o > 0; o >>= 1) s += __shfl_down_sync(0xffffffffu, s, o);
  __shared__ float red[8];
  if ((tid & 31) == 0) red[tid >> 5] = s;
  __syncthreads();
  if (tid == 0) {
    float t = 0.f;
#pragma unroll
    for (int ww = 0; ww < 8; ww++) t += red[ww];
    out[0] = t * (float)(1.0 / ((double)BATCH * INNER * INNER * 99.0));
  }
}

extern "C" void kernel_launch(void* const* d_in, const int* in_sizes, int n_in,
                              void* d_out, int out_size) {
  const float* pred = (const float*)d_in[0];
  const float* gt = (const float*)d_in[1];
  cudaFuncSetAttribute(mind_main, cudaFuncAttributeMaxDynamicSharedMemorySize,
                       SMEM_BYTES);
  dim3 grid(TILES_X, TILES_Y, BATCH);
  mind_main<<<grid, NTHREADS, SMEM_BYTES>>>(pred, gt);
  mind_reduce<<<1, 256>>>((float*)d_out);
}

// round 5
// speedup vs baseline: 1.2071x; 1.2071x over previous
#include <cuda_runtime.h>

// ---------------------------------------------------------------------------
// MIND loss, fully fused. R5 = R3 (balanced 288-CTA grid, 32x64 tile) +
// register-cached unshifted taps for the primary row-stage unit.
//  - pred/gt packed into f32x2 (FFMA2): one packed op handles both images
//  - 64-bit smem accesses conflict-free per 16-lane phase (odd pitches 81/67)
//  - M/max(M) == exp((Dmin - D)/V)  -> two passes over the 99 shifts
// ---------------------------------------------------------------------------

typedef unsigned long long u64;

namespace {
constexpr int HIMG = 384;
constexpr int WIMG = 384;
constexpr int BATCH = 4;
constexpr int INNER = 370;          // 384 - 2*7
constexpr int TILE_H = 32;
constexpr int TILE_W = 64;
constexpr int CHP = 40;             // conv-support rows (38 used + 2 pad)
constexpr int RH = 49;              // img tile rows
constexpr int RW = 79;              // img tile cols
constexpr int IP2 = 81;             // img pitch (float2 units, odd)
constexpr int RP2 = 67;             // row-buf pitch (float2 units, odd)
constexpr int NTHREADS = 256;
constexpr int TILES_X = 6;          // 6*64 = 384 >= 370
constexpr int TILES_Y = 12;         // 12*32 = 384 >= 370
constexpr int NCTAS = BATCH * TILES_X * TILES_Y;   // 288 -> one wave @ occ 2
constexpr int NUNITS = CHP * 8;                    // 320 row-conv units
constexpr int SMEM_U64 = RH * IP2 + 2 * CHP * RP2;
constexpr int SMEM_BYTES = SMEM_U64 * 8;           // 74632 B

constexpr double E98 = 0.32465246735834974;   // exp(-9/8)
constexpr double E48 = 0.60653065971263342;   // exp(-4/8)
constexpr double E18 = 0.88249690258459546;   // exp(-1/8)
constexpr double TPS = 25.132741228718345;    // 8*pi
constexpr float GX0 = (float)E98;
constexpr float GX1 = (float)E48;
constexpr float GX2 = (float)E18;             // center tap == 1
constexpr float GY0 = (float)(E98 / TPS);
constexpr float GY1 = (float)(E48 / TPS);
constexpr float GY2 = (float)(E18 / TPS);
constexpr float GY3 = (float)(1.0 / TPS);
}  // namespace

__device__ float g_partials[NCTAS];

// ---- packed f32x2 helpers (sm_100+) ----
__device__ __forceinline__ u64 bc2(float x) {
  u64 r; asm("mov.b64 %0,{%1,%1};" : "=l"(r) : "f"(x)); return r;
}
__device__ __forceinline__ u64 pk2(float a, float b) {
  u64 r; asm("mov.b64 %0,{%1,%2};" : "=l"(r) : "f"(a), "f"(b)); return r;
}
__device__ __forceinline__ void up2(u64 v, float& a, float& b) {
  asm("mov.b64 {%0,%1},%2;" : "=f"(a), "=f"(b) : "l"(v));
}
__device__ __forceinline__ u64 f2sub(u64 a, u64 b) {
  u64 r; asm("sub.rn.f32x2 %0,%1,%2;" : "=l"(r) : "l"(a), "l"(b)); return r;
}
__device__ __forceinline__ u64 f2mul(u64 a, u64 b) {
  u64 r; asm("mul.rn.f32x2 %0,%1,%2;" : "=l"(r) : "l"(a), "l"(b)); return r;
}
__device__ __forceinline__ u64 f2add(u64 a, u64 b) {
  u64 r; asm("add.rn.f32x2 %0,%1,%2;" : "=l"(r) : "l"(a), "l"(b)); return r;
}
__device__ __forceinline__ u64 f2fma(u64 a, u64 b, u64 c) {
  u64 r; asm("fma.rn.f32x2 %0,%1,%2,%3;" : "=l"(r) : "l"(a), "l"(b), "l"(c));
  return r;
}

// Horizontal 7-tap conv over precomputed dsq -> 8 outputs.
__device__ __forceinline__ void hconv8(const u64 dsq[14], u64* __restrict__ pr,
                                       u64 gx0, u64 gx1, u64 gx2) {
#pragma unroll
  for (int c = 0; c < 8; c++) {
    u64 v = f2mul(gx0, dsq[c]);
    v = f2fma(gx1, dsq[c + 1], v);
    v = f2fma(gx2, dsq[c + 2], v);
    v = f2add(v, dsq[c + 3]);  // center tap weight == 1
    v = f2fma(gx2, dsq[c + 4], v);
    v = f2fma(gx1, dsq[c + 5], v);
    v = f2fma(gx0, dsq[c + 6], v);
    pr[c] = v;
  }
}

// Primary unit: pa taps from registers.
__device__ __forceinline__ void row_cached(const u64 pa[14],
                                           const u64* __restrict__ pb,
                                           u64* __restrict__ pr,
                                           u64 gx0, u64 gx1, u64 gx2) {
  u64 dsq[14];
#pragma unroll
  for (int k = 0; k < 14; k++) {
    u64 d = f2sub(pa[k], pb[k]);
    dsq[k] = f2mul(d, d);
  }
  hconv8(dsq, pr, gx0, gx1, gx2);
}

// Overflow unit: pa taps from smem.
__device__ __forceinline__ void row_smem(const u64* __restrict__ pa,
                                         const u64* __restrict__ pb,
                                         u64* __restrict__ pr,
                                         u64 gx0, u64 gx1, u64 gx2) {
  u64 dsq[14];
#pragma unroll
  for (int k = 0; k < 14; k++) {
    u64 d = f2sub(pa[k], pb[k]);
    dsq[k] = f2mul(d, d);
  }
  hconv8(dsq, pr, gx0, gx1, gx2);
}

__device__ __forceinline__ u64 col7(const u64 rv[14], int i,
                                    u64 gy0, u64 gy1, u64 gy2, u64 gy3) {
  u64 v = f2mul(gy0, rv[i]);
  v = f2fma(gy1, rv[i + 1], v);
  v = f2fma(gy2, rv[i + 2], v);
  v = f2fma(gy3, rv[i + 3], v);
  v = f2fma(gy2, rv[i + 4], v);
  v = f2fma(gy1, rv[i + 5], v);
  v = f2fma(gy0, rv[i + 6], v);
  return v;
}

__device__ __forceinline__ void decode_shift(int si, int& sx, int& sy) {
  int t = si < 55 ? si : si + 1;   // skip (0,0) at index 55
  int q = t / 10;                  // x outer, y inner (matches reference)
  sx = q - 5;
  sy = t - q * 10 - 5;
}

extern "C" __global__ void __launch_bounds__(NTHREADS, 2)
mind_main(const float* __restrict__ pred, const float* __restrict__ gt) {
  extern __shared__ u64 smem[];
  u64* sImg = smem;
  u64* buf[2] = {smem + RH * IP2, smem + RH * IP2 + CHP * RP2};

  const int tX = blockIdx.x, tY = blockIdx.y, b = blockIdx.z;
  const int tid = threadIdx.x;
  const float* imgP = pred + b * HIMG * WIMG;
  const float* imgG = gt + b * HIMG * WIMG;

  // Load tile + halo (circular wrap), interleaving P/G into float2.
  float2* sImgF = (float2*)sImg;
  for (int i = tid; i < RH * RW; i += NTHREADS) {
    int rr = i / RW, c2 = i - rr * RW;
    int gr = tY * TILE_H + rr; if (gr >= HIMG) gr -= HIMG;
    int gc = tX * TILE_W + c2; if (gc >= WIMG) gc -= WIMG;
    sImgF[rr * IP2 + c2] = make_float2(imgP[gr * WIMG + gc],
                                       imgG[gr * WIMG + gc]);
  }
  __syncthreads();

  // Primary row-stage unit (u = tid, rows 0..31): conflict-free mapping.
  const int w0 = tid >> 5, l0 = tid & 31;
  const int j0 = ((l0 >> 3) & 3) | ((w0 & 1) << 2);
  const int r0 = (l0 & 7) | ((w0 >> 1) << 3);
  const u64* paPtr0 = sImg + (r0 + 4) * IP2 + (j0 * 8 + 4);
  u64* pr0B[2] = {buf[0] + r0 * RP2 + j0 * 8, buf[1] + r0 * RP2 + j0 * 8};

  // Overflow unit (u = tid + 256, rows 32..39) for tid < 64.
  const int u1 = tid + NTHREADS;
  const int w1 = u1 >> 5, l1 = u1 & 31;
  const int j1 = ((l1 >> 3) & 3) | ((w1 & 1) << 2);
  const int r1 = (l1 & 7) | ((w1 >> 1) << 3);
  const bool has2 = tid < (NUNITS - NTHREADS);
  const u64* paPtr1 = sImg + (r1 + 4) * IP2 + (j1 * 8 + 4);
  u64* pr1B[2] = {buf[0] + r1 * RP2 + j1 * 8, buf[1] + r1 * RP2 + j1 * 8};

  // Cache the primary unit's shift-invariant taps (reused 198 times).
  u64 pa0[14];
#pragma unroll
  for (int k = 0; k < 14; k++) pa0[k] = paPtr0[k];

  // Col-stage ownership: 64 cols x 4 groups of 8 rows.
  const int cc = tid & 63;
  const int gg = tid >> 6;
  const int coff = (gg * 8) * RP2 + cc;
  const bool cOK = (tX * TILE_W + cc) < INNER;
  const int py0 = tY * TILE_H + gg * 8;

  const u64 gx0 = bc2(GX0), gx1 = bc2(GX1), gx2 = bc2(GX2);
  const u64 gy0 = bc2(GY0), gy1 = bc2(GY1), gy2 = bc2(GY2), gy3 = bc2(GY3);

  float DmP[8], DmG[8], Vp[8], Vg[8];
#pragma unroll
  for (int i = 0; i < 8; i++) {
    DmP[i] = 3e38f; DmG[i] = 3e38f; Vp[i] = 0.f; Vg[i] = 0.f;
  }

  int sx, sy;

  // ---------------- Pass A: Dmin and cardinal sum -> invV ----------------
  decode_shift(0, sx, sy);
  {
    int d = sy * IP2 + sx;
    row_cached(pa0, paPtr0 - d, pr0B[0], gx0, gx1, gx2);
    if (has2) row_smem(paPtr1, paPtr1 - d, pr1B[0], gx0, gx1, gx2);
  }
  __syncthreads();
  for (int si = 0; si < 99; si++) {
    int cur = si & 1;
    u64 rv[14];
    {
      const u64* pc = buf[cur] + coff;
#pragma unroll
      for (int i = 0; i < 14; i++) rv[i] = pc[i * RP2];
    }
    decode_shift(si, sx, sy);
    bool card = ((sx == 0) & ((sy == 1) | (sy == -1))) |
                ((sy == 0) & ((sx == 1) | (sx == -1)));
#pragma unroll
    for (int i = 0; i < 8; i++) {
      u64 D2 = col7(rv, i, gy0, gy1, gy2, gy3);
      float dp, dg; up2(D2, dp, dg);
      DmP[i] = fminf(DmP[i], dp);
      DmG[i] = fminf(DmG[i], dg);
      if (card) { Vp[i] += dp; Vg[i] += dg; }
    }
    if (si + 1 < 99) {
      int nsx, nsy;
      decode_shift(si + 1, nsx, nsy);
      int d = nsy * IP2 + nsx;
      row_cached(pa0, paPtr0 - d, pr0B[cur ^ 1], gx0, gx1, gx2);
      if (has2) row_smem(paPtr1, paPtr1 - d, pr1B[cur ^ 1], gx0, gx1, gx2);
    }
    __syncthreads();
  }
  u64 Dmin2[8], invV2[8];
#pragma unroll
  for (int i = 0; i < 8; i++) {
    Dmin2[i] = pk2(DmP[i], DmG[i]);
    invV2[i] = pk2(1.0f / (Vp[i] * 0.25f + 1e-5f),
                   1.0f / (Vg[i] * 0.25f + 1e-5f));
  }

  // ---------------- Pass B: accumulate |Mp - Mg| ----------------
  float acc = 0.f;
  decode_shift(0, sx, sy);
  {
    int d = sy * IP2 + sx;
    row_cached(pa0, paPtr0 - d, pr0B[0], gx0, gx1, gx2);
    if (has2) row_smem(paPtr1, paPtr1 - d, pr1B[0], gx0, gx1, gx2);
  }
  __syncthreads();
  for (int si = 0; si < 99; si++) {
    int cur = si & 1;
    u64 rv[14];
    {
      const u64* pc = buf[cur] + coff;
#pragma unroll
      for (int i = 0; i < 14; i++) rv[i] = pc[i * RP2];
    }
#pragma unroll
    for (int i = 0; i < 8; i++) {
      u64 D2 = col7(rv, i, gy0, gy1, gy2, gy3);
      u64 e2 = f2mul(f2sub(Dmin2[i], D2), invV2[i]);
      float ep, eg; up2(e2, ep, eg);
      float mp = __expf(ep);
      float mg = __expf(eg);
      if (cOK && (py0 + i) < INNER) acc += fabsf(mp - mg);
    }
    if (si + 1 < 99) {
      int nsx, nsy;
      decode_shift(si + 1, nsx, nsy);
      int d = nsy * IP2 + nsx;
      row_cached(pa0, paPtr0 - d, pr0B[cur ^ 1], gx0, gx1, gx2);
      if (has2) row_smem(paPtr1, paPtr1 - d, pr1B[cur ^ 1], gx0, gx1, gx2);
    }
    __syncthreads();
  }

  // Deterministic per-CTA reduction.
#pragma unroll
  for (int o = 16; o > 0; o >>= 1) acc += __shfl_down_sync(0xffffffffu, acc, o);
  float* red = (float*)smem;   // passes done; safe reuse
  if ((tid & 31) == 0) red[tid >> 5] = acc;
  __syncthreads();
  if (tid == 0) {
    float s = 0.f;
#pragma unroll
    for (int ww = 0; ww < NTHREADS / 32; ww++) s += red[ww];
    g_partials[(b * TILES_Y + tY) * TILES_X + tX] = s;
  }
}

extern "C" __global__ void mind_reduce(float* __restrict__ out) {
  int tid = threadIdx.x;
  float s = 0.f;
  for (int i = tid; i < NCTAS; i += 256) s += g_partials[i];
#pragma unroll
  for (int o = 16; o > 0; o >>= 1) s += __shfl_down_sync(0xffffffffu, s, o);
  __shared__ float red[8];
  if ((tid & 31) == 0) red[tid >> 5] = s;
  __syncthreads();
  if (tid == 0) {
    float t = 0.f;
#pragma unroll
    for (int ww = 0; ww < 8; ww++) t += red[ww];
    out[0] = t * (float)(1.0 / ((double)BATCH * INNER * INNER * 99.0));
  }
}

extern "C" void kernel_launch(void* const* d_in, const int* in_sizes, int n_in,
                              void* d_out, int out_size) {
  const float* pred = (const float*)d_in[0];
  const float* gt = (const float*)d_in[1];
  cudaFuncSetAttribute(mind_main, cudaFuncAttributeMaxDynamicSharedMemorySize,
                       SMEM_BYTES);
  dim3 grid(TILES_X, TILES_Y, BATCH);
  mind_main<<<grid, NTHREADS, SMEM_BYTES>>>(pred, gt);
  mind_reduce<<<1, 256>>>((float*)d_out);
}